// round 4
// baseline (speedup 1.0000x reference)
#include <cuda_runtime.h>
#include <cstdint>
#include <math.h>

#define N_PIX  50176
#define C_FEAT 4224
#define C4     1056      // C_FEAT/4
#define NSEG   128
#define D_HID  1024
#define D_LOW  32
#define KSPLIT1 16
#define KSPLIT2 8
#define NCB    33        // C_FEAT / 128
#define SEGPAD 512       // padded per-segment list capacity

// ---------------- scratch (static device globals) ----------------
__device__ int   g_counts[NSEG];
__device__ int   g_perm[NSEG * SEGPAD];
__device__ float g_feat[NSEG * C_FEAT];
__device__ float g_norm2p[NSEG * NCB];
__device__ int   g_lab[NSEG];
__device__ int   g_labeled[NSEG];
__device__ int   g_lab2[NSEG];
__device__ float g_part[KSPLIT1 * 128 * 1024];
__device__ float g_h1[128 * D_HID];
__device__ float g_h2[128 * D_HID];

// ---------------- fused gather: per-segment pixel lists + counts + labels ----------------
// block b owns segment b; scans sp (L2-resident after first wave), compacts via
// warp ballot + smem counter; counts classes inline.
__global__ void __launch_bounds__(256) gather_k(const int* __restrict__ sp,
                                                const int* __restrict__ y) {
    __shared__ int cnt;
    __shared__ int rtot[8], r1[8], r2[8];
    int b = blockIdx.x;
    int t = threadIdx.x;
    int lane = t & 31, warp = t >> 5;
    if (t == 0) cnt = 0;
    __syncthreads();

    int tot = 0, c1 = 0, c2 = 0;
    int* mylist = &g_perm[b * SEGPAD];

    #pragma unroll 4
    for (int i = t; i < N_PIX; i += 256) {
        int s = sp[i];
        bool m = (s == b);
        unsigned bal = __ballot_sync(0xffffffffu, m);
        int base = 0;
        int leader = __ffs(bal) - 1;
        if (bal) {
            if (lane == leader) base = atomicAdd(&cnt, __popc(bal));
            base = __shfl_sync(0xffffffffu, base, leader);
        }
        if (m) {
            int yi = y[i];
            tot++;
            c1 += (yi == 1);
            c2 += (yi == 2);
            int pos = base + __popc(bal & ((1u << lane) - 1u));
            mylist[pos] = i;
        }
    }
    // warp reduce
    #pragma unroll
    for (int o = 16; o > 0; o >>= 1) {
        tot += __shfl_down_sync(0xffffffffu, tot, o);
        c1  += __shfl_down_sync(0xffffffffu, c1, o);
        c2  += __shfl_down_sync(0xffffffffu, c2, o);
    }
    if (lane == 0) { rtot[warp] = tot; r1[warp] = c1; r2[warp] = c2; }
    __syncthreads();
    if (t == 0) {
        int T = 0, C1 = 0, C2 = 0;
        #pragma unroll
        for (int w = 0; w < 8; w++) { T += rtot[w]; C1 += r1[w]; C2 += r2[w]; }
        int C0 = T - C1 - C2;
        int l = 0, best = C0;
        if (C1 > best) { best = C1; l = 1; }
        if (C2 > best) { best = C2; l = 2; }
        int fb = (C2 > (T >> 1)) ? 2 : ((C1 >= 1) ? 1 : 0);
        if (l == 0) l = fb;
        g_counts[b] = T;
        g_lab[b] = l;
        g_labeled[b] = (l != 0);
    }
}

// ---------------- segment sum: grid (33 col-chunks, 128 segments), 128 thr ----------------
__global__ void __launch_bounds__(128) segsum_k(const float* __restrict__ pixfeat) {
    __shared__ int   rows[512];
    __shared__ float red[4][128];
    int tid = threadIdx.x;
    int ty = tid >> 5, lane = tid & 31;
    int s = blockIdx.y;
    int cb = blockIdx.x * 128;
    int st = s * SEGPAD, cnt = g_counts[s];
    const float4* pf = (const float4*)pixfeat;
    int cb4 = cb >> 2;
    float4 acc = make_float4(0.f, 0.f, 0.f, 0.f);

    for (int c0 = 0; c0 < cnt; c0 += 512) {
        int clim = min(512, cnt - c0);
        __syncthreads();
        for (int i = tid; i < clim; i += 128) rows[i] = g_perm[st + c0 + i];
        __syncthreads();
        int main_end = clim & ~31;
        for (int g = 0; g < main_end; g += 32) {
            int base = g + ty * 8;
            float4 v[8];
            #pragma unroll
            for (int u = 0; u < 8; u++)
                v[u] = __ldcs(&pf[(size_t)rows[base + u] * C4 + cb4 + lane]);
            #pragma unroll
            for (int u = 0; u < 8; u++) {
                acc.x += v[u].x; acc.y += v[u].y; acc.z += v[u].z; acc.w += v[u].w;
            }
        }
        for (int j = main_end + ty; j < clim; j += 4) {
            float4 v = __ldcs(&pf[(size_t)rows[j] * C4 + cb4 + lane]);
            acc.x += v.x; acc.y += v.y; acc.z += v.z; acc.w += v.w;
        }
    }
    __syncthreads();
    red[ty][lane * 4 + 0] = acc.x;
    red[ty][lane * 4 + 1] = acc.y;
    red[ty][lane * 4 + 2] = acc.z;
    red[ty][lane * 4 + 3] = acc.w;
    __syncthreads();
    float sum = red[0][tid] + red[1][tid] + red[2][tid] + red[3][tid];
    float inv = 1.f / fmaxf((float)cnt, 1.f);
    float f = sum * inv;
    g_feat[s * C_FEAT + cb + tid] = f;
    __syncthreads();
    red[0][tid] = f * f;
    __syncthreads();
    for (int s2 = 64; s2 > 0; s2 >>= 1) {
        if (tid < s2) red[0][tid] += red[0][tid + s2];
        __syncthreads();
    }
    if (tid == 0) g_norm2p[s * NCB + blockIdx.x] = red[0][0];
}

// ---------------- affinity + label propagation: grid 64 blocks, rows {b, b+64} ----------------
__global__ void __launch_bounds__(128) aff_k() {
    __shared__ float4 a0s4[16], a1s4[16];
    __shared__ float4 bs4[128][17];
    __shared__ float  rn[128];
    __shared__ float  rv0[128], rv1[128];
    __shared__ int    ri0[128], ri1[128];
    int tid = threadIdx.x;
    int i0 = blockIdx.x, i1 = blockIdx.x + 64;

    {
        float n2 = 0.f;
        #pragma unroll
        for (int i = 0; i < NCB; i++) n2 += g_norm2p[tid * NCB + i];
        rn[tid] = rsqrtf(n2);
    }

    const float4* feat4 = (const float4*)g_feat;
    float acc0 = 0.f, acc1 = 0.f;

    for (int k0 = 0; k0 < C4; k0 += 16) {
        __syncthreads();
        if (tid < 16)       a0s4[tid]      = feat4[i0 * C4 + k0 + tid];
        else if (tid < 32)  a1s4[tid - 16] = feat4[i1 * C4 + k0 + (tid - 16)];
        #pragma unroll
        for (int i = 0; i < 16; i++) {
            int idx = tid + i * 128;
            int r = idx >> 4, c = idx & 15;
            bs4[r][c] = feat4[r * C4 + k0 + c];
        }
        __syncthreads();
        #pragma unroll
        for (int kk = 0; kk < 16; kk++) {
            float4 bv = bs4[tid][kk];
            float4 x = a0s4[kk];
            float4 yv = a1s4[kk];
            acc0 += x.x * bv.x + x.y * bv.y + x.z * bv.z + x.w * bv.w;
            acc1 += yv.x * bv.x + yv.y * bv.y + yv.z * bv.z + yv.w * bv.w;
        }
    }
    float rj = rn[tid];
    bool labj = (g_labeled[tid] != 0);
    float v0 = labj ? acc0 * rn[i0] * rj : -INFINITY;
    float v1 = labj ? acc1 * rn[i1] * rj : -INFINITY;

    rv0[tid] = v0; ri0[tid] = tid;
    rv1[tid] = v1; ri1[tid] = tid;
    __syncthreads();
    for (int s2 = 64; s2 > 0; s2 >>= 1) {
        if (tid < s2) {
            float a = rv0[tid + s2]; int ia = ri0[tid + s2];
            if (a > rv0[tid] || (a == rv0[tid] && ia < ri0[tid])) { rv0[tid] = a; ri0[tid] = ia; }
            float b = rv1[tid + s2]; int ib = ri1[tid + s2];
            if (b > rv1[tid] || (b == rv1[tid] && ib < ri1[tid])) { rv1[tid] = b; ri1[tid] = ib; }
        }
        __syncthreads();
    }
    if (tid == 0) {
        g_lab2[i0] = (!g_labeled[i0] && rv0[0] > 0.8f) ? g_lab[ri0[0]] : g_lab[i0];
        g_lab2[i1] = (!g_labeled[i1] && rv1[0] > 0.8f) ? g_lab[ri1[0]] : g_lab[i1];
    }
}

// ---------------- tf32 MMA GEMM (M=128), split-K partials, double-buffered ----------------
__device__ __forceinline__ unsigned tf32_of(float f) {
    unsigned u;
    asm("cvt.rna.tf32.f32 %0, %1;" : "=r"(u) : "f"(f));
    return u;
}
__device__ __forceinline__ void mma8(float& c0, float& c1, float& c2, float& c3,
                                     unsigned a0, unsigned a1, unsigned a2, unsigned a3,
                                     unsigned b0, unsigned b1) {
    asm volatile(
        "mma.sync.aligned.m16n8k8.row.col.f32.tf32.tf32.f32 "
        "{%0,%1,%2,%3},{%4,%5,%6,%7},{%8,%9},{%0,%1,%2,%3};\n"
        : "+f"(c0), "+f"(c1), "+f"(c2), "+f"(c3)
        : "r"(a0), "r"(a1), "r"(a2), "r"(a3), "r"(b0), "r"(b1));
}

template<int NSUB>
__global__ void __launch_bounds__(256) gemm_tf32_k(const float* __restrict__ A,
                                                   const float* __restrict__ B,
                                                   float* __restrict__ part,
                                                   int N, int K, int ksteps) {
    const int BN = 8 * NSUB;
    const int BELE = (8 * BN) / 256;
    __shared__ float As[128][9];
    __shared__ float Bs[8][BN + 4];
    int tid = threadIdx.x;
    int warp = tid >> 5, lane = tid & 31;
    int grp = lane >> 2, tig = lane & 3;
    int n0 = blockIdx.x * BN;
    int k_begin = blockIdx.y * ksteps * 8;

    int ar = tid >> 1;
    int ac = (tid & 1) * 4;

    float c[NSUB][4];
    #pragma unroll
    for (int i = 0; i < NSUB; i++) { c[i][0] = c[i][1] = c[i][2] = c[i][3] = 0.f; }

    float4 aReg = *(const float4*)(A + (size_t)ar * K + k_begin + ac);
    float  bReg[BELE];
    #pragma unroll
    for (int e = 0; e < BELE; e++) {
        int idx = tid + e * 256;
        int kr = idx / BN, n = idx % BN;
        bReg[e] = B[(size_t)(k_begin + kr) * N + n0 + n];
    }
    As[ar][ac + 0] = aReg.x; As[ar][ac + 1] = aReg.y;
    As[ar][ac + 2] = aReg.z; As[ar][ac + 3] = aReg.w;
    #pragma unroll
    for (int e = 0; e < BELE; e++) {
        int idx = tid + e * 256;
        Bs[idx / BN][idx % BN] = bReg[e];
    }
    __syncthreads();

    int row = 16 * warp + grp;
    for (int ks = 0; ks < ksteps; ks++) {
        if (ks + 1 < ksteps) {
            int kk = k_begin + (ks + 1) * 8;
            aReg = *(const float4*)(A + (size_t)ar * K + kk + ac);
            #pragma unroll
            for (int e = 0; e < BELE; e++) {
                int idx = tid + e * 256;
                int kr = idx / BN, n = idx % BN;
                bReg[e] = B[(size_t)(kk + kr) * N + n0 + n];
            }
        }
        unsigned a0 = tf32_of(As[row][tig]);
        unsigned a1 = tf32_of(As[row + 8][tig]);
        unsigned a2 = tf32_of(As[row][tig + 4]);
        unsigned a3 = tf32_of(As[row + 8][tig + 4]);
        #pragma unroll
        for (int ns = 0; ns < NSUB; ns++) {
            unsigned b0 = tf32_of(Bs[tig][ns * 8 + grp]);
            unsigned b1 = tf32_of(Bs[tig + 4][ns * 8 + grp]);
            mma8(c[ns][0], c[ns][1], c[ns][2], c[ns][3], a0, a1, a2, a3, b0, b1);
        }
        __syncthreads();
        if (ks + 1 < ksteps) {
            As[ar][ac + 0] = aReg.x; As[ar][ac + 1] = aReg.y;
            As[ar][ac + 2] = aReg.z; As[ar][ac + 3] = aReg.w;
            #pragma unroll
            for (int e = 0; e < BELE; e++) {
                int idx = tid + e * 256;
                Bs[idx / BN][idx % BN] = bReg[e];
            }
        }
        __syncthreads();
    }
    float* pout = part + (size_t)blockIdx.y * 128 * N;
    #pragma unroll
    for (int ns = 0; ns < NSUB; ns++) {
        int col = n0 + ns * 8 + tig * 2;
        pout[row * N + col]           = c[ns][0];
        pout[row * N + col + 1]       = c[ns][1];
        pout[(row + 8) * N + col]     = c[ns][2];
        pout[(row + 8) * N + col + 1] = c[ns][3];
    }
}

__global__ void reduce_bias_relu_k(const float* __restrict__ part,
                                   const float* __restrict__ bias,
                                   float* __restrict__ out, int N, int ksplit) {
    int idx = blockIdx.x * 256 + threadIdx.x;
    if (idx >= 128 * N) return;
    int n = idx % N;
    float s = bias[n];
    for (int k = 0; k < ksplit; k++) s += part[k * 128 * N + idx];
    out[idx] = fmaxf(s, 0.f);
}

// ---------------- layer-3 reduce + classifier head + output pack (fused) ----------------
__global__ void head3_k(const float* __restrict__ b3,
                        const float* __restrict__ wc, const float* __restrict__ bc,
                        float* __restrict__ out, int out_size) {
    int s = threadIdx.x;   // 128 segments
    float l0 = bc[0], l1 = bc[1];
    #pragma unroll
    for (int j = 0; j < D_LOW; j++) {
        float a = b3[j];
        #pragma unroll
        for (int k = 0; k < KSPLIT2; k++) a += g_part[k * 128 * D_LOW + s * D_LOW + j];
        float h = fmaxf(a, 0.f);
        l0 += h * wc[j * 2 + 0];
        l1 += h * wc[j * 2 + 1];
    }
    float m = fmaxf(l0, l1);
    float e0 = expf(l0 - m), e1 = expf(l1 - m);
    float inv = 1.f / (e0 + e1);
    out[2 * s]     = e0 * inv;
    out[2 * s + 1] = e1 * inv;
    if (out_size >= 384) out[256 + s] = (float)g_lab2[s];
}

// ---------------- launch ----------------
extern "C" void kernel_launch(void* const* d_in, const int* in_sizes, int n_in,
                              void* d_out, int out_size) {
    const float* pixfeat = (const float*)d_in[0];
    const float* w1 = (const float*)d_in[1];
    const float* b1 = (const float*)d_in[2];
    const float* w2 = (const float*)d_in[3];
    const float* b2 = (const float*)d_in[4];
    const float* w3 = (const float*)d_in[5];
    const float* b3 = (const float*)d_in[6];
    const float* wc = (const float*)d_in[7];
    const float* bc = (const float*)d_in[8];
    const int*   sp = (const int*)d_in[9];
    const int*   yy = (const int*)d_in[10];
    float* out = (float*)d_out;

    float *p_feat, *p_h1, *p_h2, *p_part;
    cudaGetSymbolAddress((void**)&p_feat, g_feat);
    cudaGetSymbolAddress((void**)&p_h1,   g_h1);
    cudaGetSymbolAddress((void**)&p_h2,   g_h2);
    cudaGetSymbolAddress((void**)&p_part, g_part);

    cudaStream_t sB;
    cudaStreamCreateWithFlags(&sB, cudaStreamNonBlocking);
    cudaEvent_t eA, eB;
    cudaEventCreateWithFlags(&eA, cudaEventDisableTiming);
    cudaEventCreateWithFlags(&eB, cudaEventDisableTiming);

    gather_k<<<NSEG, 256>>>(sp, yy);
    segsum_k<<<dim3(NCB, NSEG), 128>>>(pixfeat);

    // fork: affinity/label propagation runs concurrently with the MLP chain
    cudaEventRecord(eA, 0);
    cudaStreamWaitEvent(sB, eA, 0);
    aff_k<<<64, 128, 0, sB>>>();
    cudaEventRecord(eB, sB);

    // MLP chain on main stream
    gemm_tf32_k<8><<<dim3(D_HID / 64, KSPLIT1), 256>>>(p_feat, w1, p_part, D_HID, C_FEAT, C_FEAT / 8 / KSPLIT1);
    reduce_bias_relu_k<<<(128 * D_HID + 255) / 256, 256>>>(p_part, b1, p_h1, D_HID, KSPLIT1);
    gemm_tf32_k<8><<<dim3(D_HID / 64, KSPLIT2), 256>>>(p_h1, w2, p_part, D_HID, D_HID, D_HID / 8 / KSPLIT2);
    reduce_bias_relu_k<<<(128 * D_HID + 255) / 256, 256>>>(p_part, b2, p_h2, D_HID, KSPLIT2);
    gemm_tf32_k<4><<<dim3(1, KSPLIT2), 256>>>(p_h2, w3, p_part, D_LOW, D_HID, D_HID / 8 / KSPLIT2);

    cudaStreamWaitEvent((cudaStream_t)0, eB, 0);
    head3_k<<<1, 128>>>(b3, wc, bc, out, out_size);
}